// round 8
// baseline (speedup 1.0000x reference)
#include <cuda_runtime.h>
#include <stdint.h>

// Attention: B=256,H=32,S=16,D=64. scale=1/sqrt(8). +ones mask (cancels in softmax).
// Dropout p=0.3, jax partitionable threefry (verified R5):
//   bits[i] = out0 ^ out1 of threefry2x32(key=(0,42), x0=0, x1=i)
//   uniform = bitcast((bits>>9)|0x3f800000)-1 ; keep = uniform < 0.7f.
//
// One warp per head (R6 layout). lane = (r = lane>>1, half = lane&1).
// k,v staged in swizzled smem (2-distinct-addr broadcast loads); q read via LDG.128
// (each chunk consumed by exactly 2 lanes -> smem tile not worth it).
// PV accumulated in two 4-float4 passes to cut register pressure.

#define HEADS_PER_BLOCK 4
#define NBLOCKS         2048        // 8192 heads / 4

__device__ __forceinline__ uint32_t threefry2x32_xor_k042(uint32_t x0, uint32_t x1) {
    const uint32_t k0 = 0u;
    const uint32_t k1 = 42u;
    const uint32_t k2 = 0x1BD11BDAu ^ k0 ^ k1;
    x0 += k0; x1 += k1;
#define TF_R(R) { x0 += x1; x1 = __funnelshift_l(x1, x1, (R)); x1 ^= x0; }
    TF_R(13) TF_R(15) TF_R(26) TF_R(6)
    x0 += k1; x1 += k2 + 1u;
    TF_R(17) TF_R(29) TF_R(16) TF_R(24)
    x0 += k2; x1 += k0 + 2u;
    TF_R(13) TF_R(15) TF_R(26) TF_R(6)
    x0 += k0; x1 += k1 + 3u;
    TF_R(17) TF_R(29) TF_R(16) TF_R(24)
    x0 += k1; x1 += k2 + 4u;
    TF_R(13) TF_R(15) TF_R(26) TF_R(6)
    x0 += k2; x1 += k0 + 5u;
#undef TF_R
    return x0 ^ x1;
}

__device__ __forceinline__ float tf_uniform(uint32_t bits) {
    return __uint_as_float((bits >> 9) | 0x3f800000u) - 1.0f;
}

__global__ __launch_bounds__(128, 6)
void attn_drop_kernel(const float* __restrict__ q,
                      const float* __restrict__ k,
                      const float* __restrict__ v,
                      float* __restrict__ out) {
    // k,v only: 2 tensors * 4 heads * 4KB = 32KB -> 7-block smem cap (6 via regs)
    __shared__ float4 sk[HEADS_PER_BLOCK * 256];
    __shared__ float4 sv[HEADS_PER_BLOCK * 256];

    const int tid  = threadIdx.x;
    const int w    = tid >> 5;            // warp id = head slot within block
    const int lane = tid & 31;
    const int hd   = blockIdx.x * HEADS_PER_BLOCK + w;
    const int hb   = w * 256;             // smem f4 base for this head

    const float4* kg = reinterpret_cast<const float4*>(k) + (size_t)hd * 256;
    const float4* vg = reinterpret_cast<const float4*>(v) + (size_t)hd * 256;

    // ---- Per-warp coalesced stage of this head's k,v into swizzled smem ----
    #pragma unroll
    for (int i = 0; i < 8; i++) {
        const int f    = i * 32 + lane;           // f4 index within head
        const int row  = f >> 4;
        const int c4   = f & 15;
        const int slot = hb + row * 16 + ((c4 + row) & 15);
        sk[slot] = kg[f];
        sv[slot] = vg[f];
    }

    const int r    = lane >> 1;
    const int half = lane & 1;
    const float4* qrow = reinterpret_cast<const float4*>(q) + (size_t)hd * 256 + r * 16;

    // ---- Dropout mask (overlaps staging LDG latency): 8 threefry calls ----
    unsigned kmask = 0;
    const uint32_t fbase = (uint32_t)hd * 256u + (uint32_t)(r * 16 + half);
    #pragma unroll
    for (int j = 0; j < 8; j++) {
        const uint32_t bits = threefry2x32_xor_k042(0u, fbase + 2u * (uint32_t)j);
        kmask |= (tf_uniform(bits) < 0.7f) ? (1u << j) : 0u;
    }

    __syncwarp();

    // ---- QK^T: lane computes logits[r][2j+half], j=0..7 ----
    const float SCALE = 0.35355339059327373f;     // 1/sqrt(8)
    float acc[8];
    #pragma unroll
    for (int j = 0; j < 8; j++) acc[j] = 0.0f;

    #pragma unroll
    for (int dd = 0; dd < 16; dd++) {
        const float4 qc = qrow[dd];               // LDG.128, 2-lane dedup
        #pragma unroll
        for (int j = 0; j < 8; j++) {
            const int kr = 2 * j + half;
            const float4 kc = sk[hb + kr * 16 + ((dd + kr) & 15)];
            acc[j] = fmaf(qc.x, kc.x,
                     fmaf(qc.y, kc.y,
                     fmaf(qc.z, kc.z,
                     fmaf(qc.w, kc.w, acc[j]))));
        }
    }

    // ---- softmax over the full row (this lane + partner lane^1) ----
    float m = -1e30f;
    #pragma unroll
    for (int j = 0; j < 8; j++) {
        acc[j] = acc[j] * SCALE + 1.0f;           // additive ones mask
        m = fmaxf(m, acc[j]);
    }
    m = fmaxf(m, __shfl_xor_sync(0xffffffffu, m, 1));

    float s = 0.0f;
    #pragma unroll
    for (int j = 0; j < 8; j++) {
        acc[j] = __expf(acc[j] - m);
        s += acc[j];
    }
    s += __shfl_xor_sync(0xffffffffu, s, 1);
    const float inv = 1.0f / (s * 0.7f);          // softmax normalize + dropout scale

    float pm[8];
    #pragma unroll
    for (int j = 0; j < 8; j++)
        pm[j] = (kmask & (1u << j)) ? acc[j] * inv : 0.0f;

    // partner's 8 probabilities (other column parity)
    float po[8];
    #pragma unroll
    for (int j = 0; j < 8; j++)
        po[j] = __shfl_xor_sync(0xffffffffu, pm[j], 1);

    // ---- P @ V in two passes of 4 float4 accumulators (register relief) ----
    float4* og = reinterpret_cast<float4*>(out) + (size_t)hd * 256 + r * 16;
    #pragma unroll
    for (int pass = 0; pass < 2; pass++) {
        float4 o[4];
        #pragma unroll
        for (int u = 0; u < 4; u++) o[u] = make_float4(0.f, 0.f, 0.f, 0.f);

        #pragma unroll
        for (int t = 0; t < 16; t++) {
            const float pv = ((t & 1) == half) ? pm[t >> 1] : po[t >> 1];
            #pragma unroll
            for (int u = 0; u < 4; u++) {
                const int cc = 2 * (pass * 4 + u) + half;
                const float4 vc = sv[hb + t * 16 + ((cc + t) & 15)];
                o[u].x = fmaf(pv, vc.x, o[u].x);
                o[u].y = fmaf(pv, vc.y, o[u].y);
                o[u].z = fmaf(pv, vc.z, o[u].z);
                o[u].w = fmaf(pv, vc.w, o[u].w);
            }
        }
        #pragma unroll
        for (int u = 0; u < 4; u++)
            og[2 * (pass * 4 + u) + half] = o[u];
    }
}

extern "C" void kernel_launch(void* const* d_in, const int* in_sizes, int n_in,
                              void* d_out, int out_size) {
    const float* q = (const float*)d_in[0];
    const float* k = (const float*)d_in[1];
    const float* v = (const float*)d_in[2];
    float* out = (float*)d_out;
    (void)in_sizes; (void)n_in; (void)out_size;
    attn_drop_kernel<<<NBLOCKS, 128>>>(q, k, v, out);
}

// round 9
// speedup vs baseline: 1.1034x; 1.1034x over previous
#include <cuda_runtime.h>
#include <stdint.h>

// Attention: B=256,H=32,S=16,D=64. scale=1/sqrt(8). +ones mask (cancels in softmax).
// Dropout p=0.3, jax partitionable threefry (verified R5):
//   bits[i] = out0 ^ out1 of threefry2x32(key=(0,42), x0=0, x1=i)
//   uniform = bitcast((bits>>9)|0x3f800000)-1 ; keep = uniform < 0.7f.
//
// One warp per head. lane = (rg = lane>>2, qt = lane&3).
// Lane owns rows {rg, rg+8} and cols/chunks {4j+qt}.
// QK: 6 LDS + 32 FMA per dd ; PV: 6 LDS + 32 FMA per t  (FMA:LDS ~5.3).
// Smem swizzle slot = row*16 + ((c4+row)&15): every access pattern 1 wavefront.

#define HEADS_PER_BLOCK 4
#define NBLOCKS         2048        // 8192 heads / 4
#define PSTR            20          // ps row stride: all reads/writes bank-conflict-free

__device__ __forceinline__ uint32_t threefry2x32_xor_k042(uint32_t x0, uint32_t x1) {
    const uint32_t k0 = 0u;
    const uint32_t k1 = 42u;
    const uint32_t k2 = 0x1BD11BDAu ^ k0 ^ k1;
    x0 += k0; x1 += k1;
#define TF_R(R) { x0 += x1; x1 = __funnelshift_l(x1, x1, (R)); x1 ^= x0; }
    TF_R(13) TF_R(15) TF_R(26) TF_R(6)
    x0 += k1; x1 += k2 + 1u;
    TF_R(17) TF_R(29) TF_R(16) TF_R(24)
    x0 += k2; x1 += k0 + 2u;
    TF_R(13) TF_R(15) TF_R(26) TF_R(6)
    x0 += k0; x1 += k1 + 3u;
    TF_R(17) TF_R(29) TF_R(16) TF_R(24)
    x0 += k1; x1 += k2 + 4u;
    TF_R(13) TF_R(15) TF_R(26) TF_R(6)
    x0 += k2; x1 += k0 + 5u;
#undef TF_R
    return x0 ^ x1;
}

__device__ __forceinline__ float tf_uniform(uint32_t bits) {
    return __uint_as_float((bits >> 9) | 0x3f800000u) - 1.0f;
}

__global__ __launch_bounds__(128)
void attn_drop_kernel(const float* __restrict__ q,
                      const float* __restrict__ k,
                      const float* __restrict__ v,
                      float* __restrict__ out) {
    __shared__ float4 sq[HEADS_PER_BLOCK * 256];
    __shared__ float4 sk[HEADS_PER_BLOCK * 256];
    __shared__ float4 sv[HEADS_PER_BLOCK * 256];
    __shared__ float  ps[HEADS_PER_BLOCK][16 * PSTR];

    const int tid  = threadIdx.x;
    const int w    = tid >> 5;            // warp id = head slot within block
    const int lane = tid & 31;
    const int hd   = blockIdx.x * HEADS_PER_BLOCK + w;
    const int hb   = w * 256;

    const float4* qg = reinterpret_cast<const float4*>(q) + (size_t)hd * 256;
    const float4* kg = reinterpret_cast<const float4*>(k) + (size_t)hd * 256;
    const float4* vg = reinterpret_cast<const float4*>(v) + (size_t)hd * 256;

    // ---- Per-warp coalesced stage of this head's q,k,v into swizzled smem ----
    #pragma unroll
    for (int i = 0; i < 8; i++) {
        const int f    = i * 32 + lane;
        const int row  = f >> 4;
        const int c4   = f & 15;
        const int slot = hb + row * 16 + ((c4 + row) & 15);
        sq[slot] = qg[f];
        sk[slot] = kg[f];
        sv[slot] = vg[f];
    }

    const int rg = lane >> 2;             // row group: owns rows rg and rg+8
    const int qt = lane & 3;              // quarter: owns cols/chunks 4j+qt
    const int rA = rg;
    const int rB = rg + 8;

    // ---- Dropout masks (overlap staging LDG latency): 8 threefry calls ----
    // bit j  -> (row rA, col 4j+qt) ; bit 4+j -> (row rB, col 4j+qt)
    unsigned kmask = 0;
    {
        const uint32_t base = (uint32_t)hd * 256u + (uint32_t)qt;
        #pragma unroll
        for (int j = 0; j < 4; j++) {
            const uint32_t bA = threefry2x32_xor_k042(0u, base + (uint32_t)(rA * 16 + 4 * j));
            const uint32_t bB = threefry2x32_xor_k042(0u, base + (uint32_t)(rB * 16 + 4 * j));
            kmask |= (tf_uniform(bA) < 0.7f) ? (1u << j)       : 0u;
            kmask |= (tf_uniform(bB) < 0.7f) ? (1u << (4 + j)) : 0u;
        }
    }

    __syncwarp();

    // ---- QK^T: accA[j] = logits[rA][4j+qt], accB[j] = logits[rB][4j+qt] ----
    const float SCALE = 0.35355339059327373f;     // 1/sqrt(8)
    float accA[4] = {0.f, 0.f, 0.f, 0.f};
    float accB[4] = {0.f, 0.f, 0.f, 0.f};

    #pragma unroll
    for (int dd = 0; dd < 16; dd++) {
        const float4 qa = sq[hb + rA * 16 + ((dd + rA) & 15)];  // 8 distinct, 1 wf
        const float4 qb = sq[hb + rB * 16 + ((dd + rB) & 15)];  // 8 distinct, 1 wf
        #pragma unroll
        for (int j = 0; j < 4; j++) {
            const int c = 4 * j + qt;
            const float4 kc = sk[hb + c * 16 + ((dd + c) & 15)]; // 4 distinct, 1 wf
            accA[j] = fmaf(qa.x, kc.x, fmaf(qa.y, kc.y,
                      fmaf(qa.z, kc.z, fmaf(qa.w, kc.w, accA[j]))));
            accB[j] = fmaf(qb.x, kc.x, fmaf(qb.y, kc.y,
                      fmaf(qb.z, kc.z, fmaf(qb.w, kc.w, accB[j]))));
        }
    }

    // ---- softmax per row across the 4 qt-lanes sharing it ----
    float mA = -1e30f, mB = -1e30f;
    #pragma unroll
    for (int j = 0; j < 4; j++) {
        accA[j] = accA[j] * SCALE + 1.0f;         // additive ones mask
        accB[j] = accB[j] * SCALE + 1.0f;
        mA = fmaxf(mA, accA[j]);
        mB = fmaxf(mB, accB[j]);
    }
    mA = fmaxf(mA, __shfl_xor_sync(0xffffffffu, mA, 1));
    mA = fmaxf(mA, __shfl_xor_sync(0xffffffffu, mA, 2));
    mB = fmaxf(mB, __shfl_xor_sync(0xffffffffu, mB, 1));
    mB = fmaxf(mB, __shfl_xor_sync(0xffffffffu, mB, 2));

    float sA = 0.f, sB = 0.f;
    #pragma unroll
    for (int j = 0; j < 4; j++) {
        accA[j] = __expf(accA[j] - mA);
        accB[j] = __expf(accB[j] - mB);
        sA += accA[j];
        sB += accB[j];
    }
    sA += __shfl_xor_sync(0xffffffffu, sA, 1);
    sA += __shfl_xor_sync(0xffffffffu, sA, 2);
    sB += __shfl_xor_sync(0xffffffffu, sB, 1);
    sB += __shfl_xor_sync(0xffffffffu, sB, 2);
    const float invA = 1.0f / (sA * 0.7f);        // normalize + dropout scale
    const float invB = 1.0f / (sB * 0.7f);

    #pragma unroll
    for (int j = 0; j < 4; j++) {
        ps[w][rA * PSTR + 4 * j + qt] = (kmask & (1u << j))       ? accA[j] * invA : 0.0f;
        ps[w][rB * PSTR + 4 * j + qt] = (kmask & (1u << (4 + j))) ? accB[j] * invB : 0.0f;
    }

    __syncwarp();

    // ---- P @ V: v load shared by both rows (4 v + 2 p LDS feed 32 FMA per t) ----
    float4 oA[4], oB[4];
    #pragma unroll
    for (int u = 0; u < 4; u++) {
        oA[u] = make_float4(0.f, 0.f, 0.f, 0.f);
        oB[u] = make_float4(0.f, 0.f, 0.f, 0.f);
    }

    #pragma unroll
    for (int t = 0; t < 16; t++) {
        const float pA = ps[w][rA * PSTR + t];    // 8 distinct banks, broadcast
        const float pB = ps[w][rB * PSTR + t];
        #pragma unroll
        for (int u = 0; u < 4; u++) {
            const int cu = 4 * u + qt;
            const float4 vc = sv[hb + t * 16 + ((cu + t) & 15)]; // 4 distinct, 1 wf
            oA[u].x = fmaf(pA, vc.x, oA[u].x);
            oA[u].y = fmaf(pA, vc.y, oA[u].y);
            oA[u].z = fmaf(pA, vc.z, oA[u].z);
            oA[u].w = fmaf(pA, vc.w, oA[u].w);
            oB[u].x = fmaf(pB, vc.x, oB[u].x);
            oB[u].y = fmaf(pB, vc.y, oB[u].y);
            oB[u].z = fmaf(pB, vc.z, oB[u].z);
            oB[u].w = fmaf(pB, vc.w, oB[u].w);
        }
    }

    // ---- stores: full 64B per (row, quad-group) ----
    float4* og = reinterpret_cast<float4*>(out) + (size_t)hd * 256;
    #pragma unroll
    for (int u = 0; u < 4; u++) {
        og[rA * 16 + 4 * u + qt] = oA[u];
        og[rB * 16 + 4 * u + qt] = oB[u];
    }
}

extern "C" void kernel_launch(void* const* d_in, const int* in_sizes, int n_in,
                              void* d_out, int out_size) {
    const float* q = (const float*)d_in[0];
    const float* k = (const float*)d_in[1];
    const float* v = (const float*)d_in[2];
    float* out = (float*)d_out;
    (void)in_sizes; (void)n_in; (void)out_size;
    attn_drop_kernel<<<NBLOCKS, 128>>>(q, k, v, out);
}

// round 11
// speedup vs baseline: 1.2965x; 1.1750x over previous
#include <cuda_runtime.h>
#include <stdint.h>

// Attention: B=256,H=32,S=16,D=64. scale=1/sqrt(8). +ones mask (cancels in softmax).
// Dropout p=0.3, jax partitionable threefry (verified R5):
//   bits[i] = out0 ^ out1 of threefry2x32(key=(0,42), x0=0, x1=i)
//   uniform = bitcast((bits>>9)|0x3f800000)-1 ; keep = uniform < 0.7f.
//
// Warp-autonomous persistent pipeline: each warp grid-strides over heads with a
// private 2-stage cp.async double buffer (12KB/stage). Compute blocking = R9:
// lane (rg = lane>>2, qt = lane&3) owns rows {rg, rg+8} and cols/chunks {4j+qt}.
// Swizzle slot = row*16 + ((c4+row)&15): every smem access is 1 wavefront.

#define NBLOCKS      304
#define WARPS_TOTAL  (NBLOCKS * 4)          // 1216
#define STAGE_F4     768                    // 256 q + 256 k + 256 v float4 slots
#define WARP_F4      (2 * STAGE_F4)         // double buffered
#define SMEM_BYTES   (4 * WARP_F4 * 16)     // 96 KB per 128-thread block

__device__ __forceinline__ uint32_t threefry2x32_xor_k042(uint32_t x0, uint32_t x1) {
    const uint32_t k0 = 0u;
    const uint32_t k1 = 42u;
    const uint32_t k2 = 0x1BD11BDAu ^ k0 ^ k1;
    x0 += k0; x1 += k1;
#define TF_R(R) { x0 += x1; x1 = __funnelshift_l(x1, x1, (R)); x1 ^= x0; }
    TF_R(13) TF_R(15) TF_R(26) TF_R(6)
    x0 += k1; x1 += k2 + 1u;
    TF_R(17) TF_R(29) TF_R(16) TF_R(24)
    x0 += k2; x1 += k0 + 2u;
    TF_R(13) TF_R(15) TF_R(26) TF_R(6)
    x0 += k0; x1 += k1 + 3u;
    TF_R(17) TF_R(29) TF_R(16) TF_R(24)
    x0 += k1; x1 += k2 + 4u;
    TF_R(13) TF_R(15) TF_R(26) TF_R(6)
    x0 += k2; x1 += k0 + 5u;
#undef TF_R
    return x0 ^ x1;
}

__device__ __forceinline__ float tf_uniform(uint32_t bits) {
    return __uint_as_float((bits >> 9) | 0x3f800000u) - 1.0f;
}

// Issue one head's q,k,v into a stage buffer via cp.async (per-lane 24 x 16B).
__device__ __forceinline__ void stage_head(float4* stage, int lane,
                                           const float4* __restrict__ qg,
                                           const float4* __restrict__ kg,
                                           const float4* __restrict__ vg) {
    #pragma unroll
    for (int i = 0; i < 8; i++) {
        const int f    = i * 32 + lane;
        const int row  = f >> 4;
        const int c4   = f & 15;
        const int slot = row * 16 + ((c4 + row) & 15);
        const uint32_t dq = (uint32_t)__cvta_generic_to_shared(stage + slot);
        asm volatile("cp.async.cg.shared.global [%0], [%1], 16;" :: "r"(dq),               "l"(qg + f));
        asm volatile("cp.async.cg.shared.global [%0], [%1], 16;" :: "r"(dq + 256u * 16u),  "l"(kg + f));
        asm volatile("cp.async.cg.shared.global [%0], [%1], 16;" :: "r"(dq + 512u * 16u),  "l"(vg + f));
    }
    asm volatile("cp.async.commit_group;");
}

__global__ __launch_bounds__(128)
void attn_drop_kernel(const float* __restrict__ q,
                      const float* __restrict__ k,
                      const float* __restrict__ v,
                      float* __restrict__ out) {
    extern __shared__ float4 smem[];

    const int tid  = threadIdx.x;
    const int w    = tid >> 5;
    const int lane = tid & 31;
    float4* buf = smem + w * WARP_F4;     // this warp's private double buffer

    const int rg = lane >> 2;             // row group: owns rows rg and rg+8
    const int qt = lane & 3;              // quarter: owns cols/chunks 4j+qt
    const int rA = rg;
    const int rB = rg + 8;

    const float4* qg = reinterpret_cast<const float4*>(q);
    const float4* kg = reinterpret_cast<const float4*>(k);
    const float4* vg = reinterpret_cast<const float4*>(v);
    float4*       og = reinterpret_cast<float4*>(out);

    const float SCALE = 0.35355339059327373f;     // 1/sqrt(8)

    int h = blockIdx.x * 4 + w;
    // ---- prologue: prefetch first head into stage 0 ----
    stage_head(buf, lane, qg + (size_t)h * 256, kg + (size_t)h * 256, vg + (size_t)h * 256);
    int s = 0;

    for (; h < 8192; h += WARPS_TOTAL) {
        const int  hn       = h + WARPS_TOTAL;
        const bool has_next = hn < 8192;

        __syncwarp();                     // prior iter's reads of buf[s^1] complete
        if (has_next)
            stage_head(buf + (s ^ 1) * STAGE_F4, lane,
                       qg + (size_t)hn * 256, kg + (size_t)hn * 256, vg + (size_t)hn * 256);

        // ---- threefry masks for head h (pure ALU; overlaps pending cp.async) ----
        unsigned kmask = 0;
        {
            const uint32_t base = (uint32_t)h * 256u + (uint32_t)qt;
            #pragma unroll
            for (int j = 0; j < 4; j++) {
                const uint32_t bA = threefry2x32_xor_k042(0u, base + (uint32_t)(rA * 16 + 4 * j));
                const uint32_t bB = threefry2x32_xor_k042(0u, base + (uint32_t)(rB * 16 + 4 * j));
                kmask |= (tf_uniform(bA) < 0.7f) ? (1u << j)       : 0u;
                kmask |= (tf_uniform(bB) < 0.7f) ? (1u << (4 + j)) : 0u;
            }
        }

        if (has_next) { asm volatile("cp.async.wait_group 1;" ::: "memory"); }
        else          { asm volatile("cp.async.wait_group 0;" ::: "memory"); }
        __syncwarp();                     // lane-issued data visible warp-wide

        const float4* SQ = buf + s * STAGE_F4;
        const float4* SK = SQ + 256;
        const float4* SV = SQ + 512;

        // ---- QK^T: accA[j] = logits[rA][4j+qt], accB[j] = logits[rB][4j+qt] ----
        float accA[4] = {0.f, 0.f, 0.f, 0.f};
        float accB[4] = {0.f, 0.f, 0.f, 0.f};

        #pragma unroll
        for (int dd = 0; dd < 16; dd++) {
            const float4 qa = SQ[rA * 16 + ((dd + rA) & 15)];   // 8 distinct, 1 wf
            const float4 qb = SQ[rB * 16 + ((dd + rB) & 15)];
            #pragma unroll
            for (int j = 0; j < 4; j++) {
                const int c = 4 * j + qt;
                const float4 kc = SK[c * 16 + ((dd + c) & 15)]; // 4 distinct, 1 wf
                accA[j] = fmaf(qa.x, kc.x, fmaf(qa.y, kc.y,
                          fmaf(qa.z, kc.z, fmaf(qa.w, kc.w, accA[j]))));
                accB[j] = fmaf(qb.x, kc.x, fmaf(qb.y, kc.y,
                          fmaf(qb.z, kc.z, fmaf(qb.w, kc.w, accB[j]))));
            }
        }

        // ---- softmax per row across the 4 qt-lanes sharing it ----
        float mA = -1e30f, mB = -1e30f;
        #pragma unroll
        for (int j = 0; j < 4; j++) {
            accA[j] = accA[j] * SCALE + 1.0f;     // additive ones mask
            accB[j] = accB[j] * SCALE + 1.0f;
            mA = fmaxf(mA, accA[j]);
            mB = fmaxf(mB, accB[j]);
        }
        mA = fmaxf(mA, __shfl_xor_sync(0xffffffffu, mA, 1));
        mA = fmaxf(mA, __shfl_xor_sync(0xffffffffu, mA, 2));
        mB = fmaxf(mB, __shfl_xor_sync(0xffffffffu, mB, 1));
        mB = fmaxf(mB, __shfl_xor_sync(0xffffffffu, mB, 2));

        float sA = 0.f, sB = 0.f;
        #pragma unroll
        for (int j = 0; j < 4; j++) {
            accA[j] = __expf(accA[j] - mA);
            accB[j] = __expf(accB[j] - mB);
            sA += accA[j];
            sB += accB[j];
        }
        sA += __shfl_xor_sync(0xffffffffu, sA, 1);
        sA += __shfl_xor_sync(0xffffffffu, sA, 2);
        sB += __shfl_xor_sync(0xffffffffu, sB, 1);
        sB += __shfl_xor_sync(0xffffffffu, sB, 2);
        const float invA = 1.0f / (sA * 0.7f);    // normalize + dropout scale
        const float invB = 1.0f / (sB * 0.7f);

        float pmA[4], pmB[4];
        #pragma unroll
        for (int j = 0; j < 4; j++) {
            pmA[j] = (kmask & (1u << j))       ? accA[j] * invA : 0.0f;
            pmB[j] = (kmask & (1u << (4 + j))) ? accB[j] * invB : 0.0f;
        }

        // ---- P @ V: p broadcast via width-4 shfl; v load shared by both rows ----
        float4 oA[4], oB[4];
        #pragma unroll
        for (int u = 0; u < 4; u++) {
            oA[u] = make_float4(0.f, 0.f, 0.f, 0.f);
            oB[u] = make_float4(0.f, 0.f, 0.f, 0.f);
        }

        #pragma unroll
        for (int t = 0; t < 16; t++) {
            const float pA = __shfl_sync(0xffffffffu, pmA[t >> 2], t & 3, 4);
            const float pB = __shfl_sync(0xffffffffu, pmB[t >> 2], t & 3, 4);
            #pragma unroll
            for (int u = 0; u < 4; u++) {
                const int cu = 4 * u + qt;
                const float4 vc = SV[t * 16 + ((cu + t) & 15)]; // 4 distinct, 1 wf
                oA[u].x = fmaf(pA, vc.x, oA[u].x);
                oA[u].y = fmaf(pA, vc.y, oA[u].y);
                oA[u].z = fmaf(pA, vc.z, oA[u].z);
                oA[u].w = fmaf(pA, vc.w, oA[u].w);
                oB[u].x = fmaf(pB, vc.x, oB[u].x);
                oB[u].y = fmaf(pB, vc.y, oB[u].y);
                oB[u].z = fmaf(pB, vc.z, oB[u].z);
                oB[u].w = fmaf(pB, vc.w, oB[u].w);
            }
        }

        // ---- stores: full 64B per (row, quad-group) ----
        float4* oh = og + (size_t)h * 256;
        #pragma unroll
        for (int u = 0; u < 4; u++) {
            oh[rA * 16 + 4 * u + qt] = oA[u];
            oh[rB * 16 + 4 * u + qt] = oB[u];
        }

        s ^= 1;
    }
}

extern "C" void kernel_launch(void* const* d_in, const int* in_sizes, int n_in,
                              void* d_out, int out_size) {
    const float* q = (const float*)d_in[0];
    const float* k = (const float*)d_in[1];
    const float* v = (const float*)d_in[2];
    float* out = (float*)d_out;
    (void)in_sizes; (void)n_in; (void)out_size;
    cudaFuncSetAttribute(attn_drop_kernel,
                         cudaFuncAttributeMaxDynamicSharedMemorySize, SMEM_BYTES);
    attn_drop_kernel<<<NBLOCKS, 128, SMEM_BYTES>>>(q, k, v, out);
}

// round 14
// speedup vs baseline: 1.3645x; 1.0525x over previous
#include <cuda_runtime.h>
#include <stdint.h>

// Attention: B=256,H=32,S=16,D=64. scale=1/sqrt(8). +ones mask (cancels in softmax).
// Dropout p=0.3, jax partitionable threefry (verified R5):
//   bits[i] = out0 ^ out1 of threefry2x32(key=(0,42), x0=0, x1=i)
//   uniform = bitcast((bits>>9)|0x3f800000)-1 ; keep = uniform < 0.7f.
//
// Warp-autonomous persistent pipeline, SINGLE-buffered q,k,v (12KB/warp) with
// phase-split prefetch: q,k(h+1) issued after QK(h); v(h+1) after PV(h).
// Two cp.async commit groups per head; wait_group 1 at QK releases q,k while the
// v group stays in flight. 48KB/block -> 4 blocks/SM = 16 warps (2x R11 occ).
// Compute blocking (R9/R11): lane (rg=lane>>2, qt=lane&3) owns rows {rg, rg+8},
// cols/chunks {4j+qt}. Swizzle slot = row*16 + ((c4+row)&15): all LDS 1 wavefront.

#define NBLOCKS      592
#define WARPS_TOTAL  (NBLOCKS * 4)          // 2368
#define WARP_F4      768                    // 256 q + 256 k + 256 v float4 slots
#define SMEM_BYTES   (4 * WARP_F4 * 16)     // 48 KB per 128-thread block

__device__ __forceinline__ uint32_t threefry2x32_xor_k042(uint32_t x0, uint32_t x1) {
    const uint32_t k0 = 0u;
    const uint32_t k1 = 42u;
    const uint32_t k2 = 0x1BD11BDAu ^ k0 ^ k1;
    x0 += k0; x1 += k1;
#define TF_R(R) { x0 += x1; x1 = __funnelshift_l(x1, x1, (R)); x1 ^= x0; }
    TF_R(13) TF_R(15) TF_R(26) TF_R(6)
    x0 += k1; x1 += k2 + 1u;
    TF_R(17) TF_R(29) TF_R(16) TF_R(24)
    x0 += k2; x1 += k0 + 2u;
    TF_R(13) TF_R(15) TF_R(26) TF_R(6)
    x0 += k0; x1 += k1 + 3u;
    TF_R(17) TF_R(29) TF_R(16) TF_R(24)
    x0 += k1; x1 += k2 + 4u;
    TF_R(13) TF_R(15) TF_R(26) TF_R(6)
    x0 += k2; x1 += k0 + 5u;
#undef TF_R
    return x0 ^ x1;
}

__device__ __forceinline__ float tf_uniform(uint32_t bits) {
    return __uint_as_float((bits >> 9) | 0x3f800000u) - 1.0f;
}

// Issue q,k of one head into the warp buffer (group committed by caller pattern).
__device__ __forceinline__ void stage_qk(float4* buf, int lane,
                                         const float4* __restrict__ qg,
                                         const float4* __restrict__ kg) {
    #pragma unroll
    for (int i = 0; i < 8; i++) {
        const int f    = i * 32 + lane;
        const int row  = f >> 4;
        const int c4   = f & 15;
        const int slot = row * 16 + ((c4 + row) & 15);
        const uint32_t d = (uint32_t)__cvta_generic_to_shared(buf + slot);
        asm volatile("cp.async.cg.shared.global [%0], [%1], 16;" :: "r"(d),              "l"(qg + f));
        asm volatile("cp.async.cg.shared.global [%0], [%1], 16;" :: "r"(d + 256u * 16u), "l"(kg + f));
    }
    asm volatile("cp.async.commit_group;");
}

__device__ __forceinline__ void stage_v(float4* buf, int lane,
                                        const float4* __restrict__ vg) {
    #pragma unroll
    for (int i = 0; i < 8; i++) {
        const int f    = i * 32 + lane;
        const int row  = f >> 4;
        const int c4   = f & 15;
        const int slot = row * 16 + ((c4 + row) & 15);
        const uint32_t d = (uint32_t)__cvta_generic_to_shared(buf + 512 + slot);
        asm volatile("cp.async.cg.shared.global [%0], [%1], 16;" :: "r"(d), "l"(vg + f));
    }
    asm volatile("cp.async.commit_group;");
}

__global__ __launch_bounds__(128, 4)
void attn_drop_kernel(const float* __restrict__ q,
                      const float* __restrict__ k,
                      const float* __restrict__ v,
                      float* __restrict__ out) {
    extern __shared__ float4 smem[];

    const int tid  = threadIdx.x;
    const int w    = tid >> 5;
    const int lane = tid & 31;
    float4* buf = smem + w * WARP_F4;     // this warp's private q|k|v buffer

    const int rg = lane >> 2;             // row group: owns rows rg and rg+8
    const int qt = lane & 3;              // quarter: owns cols/chunks 4j+qt
    const int rA = rg;
    const int rB = rg + 8;

    const float4* qg = reinterpret_cast<const float4*>(q);
    const float4* kg = reinterpret_cast<const float4*>(k);
    const float4* vg = reinterpret_cast<const float4*>(v);
    float4*       og = reinterpret_cast<float4*>(out);

    const float SCALE = 0.35355339059327373f;     // 1/sqrt(8)

    const int h0 = blockIdx.x * 4 + w;
    if (h0 >= 8192) return;

    // ---- prologue: group A = q,k(h0); group B = v(h0) ----
    stage_qk(buf, lane, qg + (size_t)h0 * 256, kg + (size_t)h0 * 256);
    stage_v (buf, lane, vg + (size_t)h0 * 256);

    for (int h = h0; h < 8192; h += WARPS_TOTAL) {
        const int  hn       = h + WARPS_TOTAL;
        const bool has_next = hn < 8192;

        // ---- threefry masks for head h (pure ALU; overlaps in-flight cp.async) ----
        unsigned kmask = 0;
        {
            const uint32_t base = (uint32_t)h * 256u + (uint32_t)qt;
            #pragma unroll
            for (int j = 0; j < 4; j++) {
                const uint32_t bA = threefry2x32_xor_k042(0u, base + (uint32_t)(rA * 16 + 4 * j));
                const uint32_t bB = threefry2x32_xor_k042(0u, base + (uint32_t)(rB * 16 + 4 * j));
                kmask |= (tf_uniform(bA) < 0.7f) ? (1u << j)       : 0u;
                kmask |= (tf_uniform(bB) < 0.7f) ? (1u << (4 + j)) : 0u;
            }
        }

        // q,k(h) ready; v group may remain in flight
        asm volatile("cp.async.wait_group 1;" ::: "memory");
        __syncwarp();

        const float4* SQ = buf;
        const float4* SK = buf + 256;
        const float4* SV = buf + 512;

        // ---- QK^T: accA[j] = logits[rA][4j+qt], accB[j] = logits[rB][4j+qt] ----
        float accA[4] = {0.f, 0.f, 0.f, 0.f};
        float accB[4] = {0.f, 0.f, 0.f, 0.f};

        #pragma unroll
        for (int dd = 0; dd < 16; dd++) {
            const float4 qa = SQ[rA * 16 + ((dd + rA) & 15)];   // 8 distinct, 1 wf
            const float4 qb = SQ[rB * 16 + ((dd + rB) & 15)];
            #pragma unroll
            for (int j = 0; j < 4; j++) {
                const int c = 4 * j + qt;
                const float4 kc = SK[c * 16 + ((dd + c) & 15)]; // 4 distinct, 1 wf
                accA[j] = fmaf(qa.x, kc.x, fmaf(qa.y, kc.y,
                          fmaf(qa.z, kc.z, fmaf(qa.w, kc.w, accA[j]))));
                accB[j] = fmaf(qb.x, kc.x, fmaf(qb.y, kc.y,
                          fmaf(qb.z, kc.z, fmaf(qb.w, kc.w, accB[j]))));
            }
        }

        // q,k buffers dead -> prefetch next head's q,k (group A)
        __syncwarp();
        if (has_next)
            stage_qk(buf, lane, qg + (size_t)hn * 256, kg + (size_t)hn * 256);

        // ---- softmax per row across the 4 qt-lanes sharing it ----
        float mA = -1e30f, mB = -1e30f;
        #pragma unroll
        for (int j = 0; j < 4; j++) {
            accA[j] = accA[j] * SCALE + 1.0f;     // additive ones mask
            accB[j] = accB[j] * SCALE + 1.0f;
            mA = fmaxf(mA, accA[j]);
            mB = fmaxf(mB, accB[j]);
        }
        mA = fmaxf(mA, __shfl_xor_sync(0xffffffffu, mA, 1));
        mA = fmaxf(mA, __shfl_xor_sync(0xffffffffu, mA, 2));
        mB = fmaxf(mB, __shfl_xor_sync(0xffffffffu, mB, 1));
        mB = fmaxf(mB, __shfl_xor_sync(0xffffffffu, mB, 2));

        float sA = 0.f, sB = 0.f;
        #pragma unroll
        for (int j = 0; j < 4; j++) {
            accA[j] = __expf(accA[j] - mA);
            accB[j] = __expf(accB[j] - mB);
            sA += accA[j];
            sB += accB[j];
        }
        sA += __shfl_xor_sync(0xffffffffu, sA, 1);
        sA += __shfl_xor_sync(0xffffffffu, sA, 2);
        sB += __shfl_xor_sync(0xffffffffu, sB, 1);
        sB += __shfl_xor_sync(0xffffffffu, sB, 2);
        const float invA = 1.0f / (sA * 0.7f);    // normalize + dropout scale
        const float invB = 1.0f / (sB * 0.7f);

        float pmA[4], pmB[4];
        #pragma unroll
        for (int j = 0; j < 4; j++) {
            pmA[j] = (kmask & (1u << j))       ? accA[j] * invA : 0.0f;
            pmB[j] = (kmask & (1u << (4 + j))) ? accB[j] * invB : 0.0f;
        }

        // v(h) ready: allow only the newest group (q,k(h+1)) to stay pending
        if (has_next) { asm volatile("cp.async.wait_group 1;" ::: "memory"); }
        else          { asm volatile("cp.async.wait_group 0;" ::: "memory"); }
        __syncwarp();

        // ---- P @ V: p broadcast via width-4 shfl; v load shared by both rows ----
        float4 oA[4], oB[4];
        #pragma unroll
        for (int u = 0; u < 4; u++) {
            oA[u] = make_float4(0.f, 0.f, 0.f, 0.f);
            oB[u] = make_float4(0.f, 0.f, 0.f, 0.f);
        }

        #pragma unroll
        for (int t = 0; t < 16; t++) {
            const float pA = __shfl_sync(0xffffffffu, pmA[t >> 2], t & 3, 4);
            const float pB = __shfl_sync(0xffffffffu, pmB[t >> 2], t & 3, 4);
            #pragma unroll
            for (int u = 0; u < 4; u++) {
                const int cu = 4 * u + qt;
                const float4 vc = SV[t * 16 + ((cu + t) & 15)]; // 4 distinct, 1 wf
                oA[u].x = fmaf(pA, vc.x, oA[u].x);
                oA[u].y = fmaf(pA, vc.y, oA[u].y);
                oA[u].z = fmaf(pA, vc.z, oA[u].z);
                oA[u].w = fmaf(pA, vc.w, oA[u].w);
                oB[u].x = fmaf(pB, vc.x, oB[u].x);
                oB[u].y = fmaf(pB, vc.y, oB[u].y);
                oB[u].z = fmaf(pB, vc.z, oB[u].z);
                oB[u].w = fmaf(pB, vc.w, oB[u].w);
            }
        }

        // v buffer dead -> prefetch next head's v (group B)
        __syncwarp();
        if (has_next)
            stage_v(buf, lane, vg + (size_t)hn * 256);

        // ---- stores: full 64B per (row, quad-group) ----
        float4* oh = og + (size_t)h * 256;
        #pragma unroll
        for (int u = 0; u < 4; u++) {
            oh[rA * 16 + 4 * u + qt] = oA[u];
            oh[rB * 16 + 4 * u + qt] = oB[u];
        }
    }
}

extern "C" void kernel_launch(void* const* d_in, const int* in_sizes, int n_in,
                              void* d_out, int out_size) {
    const float* q = (const float*)d_in[0];
    const float* k = (const float*)d_in[1];
    const float* v = (const float*)d_in[2];
    float* out = (float*)d_out;
    (void)in_sizes; (void)n_in; (void)out_size;
    cudaFuncSetAttribute(attn_drop_kernel,
                         cudaFuncAttributeMaxDynamicSharedMemorySize, SMEM_BYTES);
    attn_drop_kernel<<<NBLOCKS, 128, SMEM_BYTES>>>(q, k, v, out);
}